// round 3
// baseline (speedup 1.0000x reference)
#include <cuda_runtime.h>
#include <cstdint>

// Problem constants
constexpr int Bb  = 4;
constexpr int Nn  = 2048;
constexpr int DIM = 1024;
constexpr int Hh  = 16;
constexpr int DH  = 64;
// scale = DH^-0.5 = 0.125 (exact power of two)

// Scratch (allocation-free rule: __device__ globals)
__device__ float g_ztu[(size_t)Bb * Hh * Nn * DH];   // [b,h,n,d]  32 MB
__device__ float g_ssa[(size_t)Bb * Nn * DIM];       // [b,n,k]    32 MB

__device__ __forceinline__ uint32_t f2tf(float x) {
    uint32_t r;
    asm("cvt.rna.tf32.f32 %0, %1;" : "=r"(r) : "f"(x));
    return r;
}

__device__ __forceinline__ void mma_tf32(float* c,
                                         uint32_t a0, uint32_t a1, uint32_t a2, uint32_t a3,
                                         uint32_t b0, uint32_t b1) {
    asm volatile(
        "mma.sync.aligned.m16n8k8.row.col.f32.tf32.tf32.f32 "
        "{%0,%1,%2,%3},{%4,%5,%6,%7},{%8,%9},{%0,%1,%2,%3};"
        : "+f"(c[0]), "+f"(c[1]), "+f"(c[2]), "+f"(c[3])
        : "r"(a0), "r"(a1), "r"(a2), "r"(a3), "r"(b0), "r"(b1));
}

__device__ __forceinline__ void split_store(uint32_t* hi, uint32_t* lo, int idx, float x) {
    uint32_t h = f2tf(x);
    hi[idx] = h;
    lo[idx] = f2tf(x - __uint_as_float(h));
}

// ---------------------------------------------------------------------------
// tf32x3 GEMM.  MODE 0: C = A @ W^T, scatter epilogue into g_ztu[b,h,n,d]
//               MODE 1: C = g_ssa @ W, plain row-major epilogue to Cout
// BT = 1: B operand read as W[j][c] (transposed);  BT = 0: W[k][j] direct.
// Tiles: BM=128, BN=128, BK=32.  256 threads = 8 warps, warp tile 64x32.
// ---------------------------------------------------------------------------
template <int BT, int MODE>
__global__ __launch_bounds__(256, 1)
void gemm_tf32x3(const float* __restrict__ Ain, const float* __restrict__ Bm,
                 float* __restrict__ Cout) {
    extern __shared__ uint32_t sm[];
    constexpr int LDA = 36;                 // 36 % 32 == 4 -> conflict-free A frags
    constexpr int LDB = BT ? 36 : 136;      // 136 % 32 == 8 -> conflict-free B frags
    constexpr int ASZ = 128 * LDA;
    constexpr int BSZ = BT ? 128 * LDB : 32 * LDB;
    uint32_t* Ah = sm;
    uint32_t* Al = Ah + ASZ;
    uint32_t* Bh = Al + ASZ;
    uint32_t* Bl = Bh + BSZ;

    const float* A = (MODE == 0) ? Ain : g_ssa;

    const int tid  = threadIdx.x;
    const int lane = tid & 31;
    const int warp = tid >> 5;
    const int g    = lane >> 2;   // group id 0..7
    const int tg   = lane & 3;    // thread-in-group 0..3
    const int wm   = warp >> 2;   // 0..1
    const int wn   = warp & 3;    // 0..3
    const int m0   = blockIdx.y * 128;
    const int n0   = blockIdx.x * 128;

    float c[4][4][4];
#pragma unroll
    for (int mt = 0; mt < 4; mt++)
#pragma unroll
        for (int nt = 0; nt < 4; nt++)
#pragma unroll
            for (int e = 0; e < 4; e++) c[mt][nt][e] = 0.0f;

    for (int kt = 0; kt < DIM / 32; kt++) {
        // ---- load A tile (128 x 32) ----
#pragma unroll
        for (int i = 0; i < 4; i++) {
            int idx = tid + i * 256;
            int r = idx >> 3, c4 = (idx & 7) << 2;
            float4 v = *(const float4*)(A + (size_t)(m0 + r) * DIM + kt * 32 + c4);
            int o = r * LDA + c4;
            split_store(Ah, Al, o + 0, v.x);
            split_store(Ah, Al, o + 1, v.y);
            split_store(Ah, Al, o + 2, v.z);
            split_store(Ah, Al, o + 3, v.w);
        }
        // ---- load B tile ----
#pragma unroll
        for (int i = 0; i < 4; i++) {
            int idx = tid + i * 256;
            if (BT) {
                int r = idx >> 3, c4 = (idx & 7) << 2;
                float4 v = *(const float4*)(Bm + (size_t)(n0 + r) * DIM + kt * 32 + c4);
                int o = r * LDB + c4;
                split_store(Bh, Bl, o + 0, v.x);
                split_store(Bh, Bl, o + 1, v.y);
                split_store(Bh, Bl, o + 2, v.z);
                split_store(Bh, Bl, o + 3, v.w);
            } else {
                int r = idx >> 5, c4 = (idx & 31) << 2;
                float4 v = *(const float4*)(Bm + (size_t)(kt * 32 + r) * DIM + n0 + c4);
                int o = r * LDB + c4;
                split_store(Bh, Bl, o + 0, v.x);
                split_store(Bh, Bl, o + 1, v.y);
                split_store(Bh, Bl, o + 2, v.z);
                split_store(Bh, Bl, o + 3, v.w);
            }
        }
        __syncthreads();

#pragma unroll
        for (int ks = 0; ks < 4; ks++) {
            uint32_t ah[4][4], alr[4][4], bh[4][2], bl[4][2];
#pragma unroll
            for (int mt = 0; mt < 4; mt++) {
                int rb = (wm * 64 + mt * 16 + g) * LDA + ks * 8 + tg;
                ah[mt][0]  = Ah[rb];
                ah[mt][1]  = Ah[rb + 8 * LDA];
                ah[mt][2]  = Ah[rb + 4];
                ah[mt][3]  = Ah[rb + 8 * LDA + 4];
                alr[mt][0] = Al[rb];
                alr[mt][1] = Al[rb + 8 * LDA];
                alr[mt][2] = Al[rb + 4];
                alr[mt][3] = Al[rb + 8 * LDA + 4];
            }
#pragma unroll
            for (int nt = 0; nt < 4; nt++) {
                if (BT) {
                    int rb = (wn * 32 + nt * 8 + g) * LDB + ks * 8 + tg;
                    bh[nt][0] = Bh[rb];
                    bh[nt][1] = Bh[rb + 4];
                    bl[nt][0] = Bl[rb];
                    bl[nt][1] = Bl[rb + 4];
                } else {
                    int rb = (ks * 8 + tg) * LDB + wn * 32 + nt * 8 + g;
                    bh[nt][0] = Bh[rb];
                    bh[nt][1] = Bh[rb + 4 * LDB];
                    bl[nt][0] = Bl[rb];
                    bl[nt][1] = Bl[rb + 4 * LDB];
                }
            }
#pragma unroll
            for (int mt = 0; mt < 4; mt++)
#pragma unroll
                for (int nt = 0; nt < 4; nt++) {
                    mma_tf32(c[mt][nt], ah[mt][0], ah[mt][1], ah[mt][2], ah[mt][3],
                             bh[nt][0], bh[nt][1]);
                    mma_tf32(c[mt][nt], ah[mt][0], ah[mt][1], ah[mt][2], ah[mt][3],
                             bl[nt][0], bl[nt][1]);
                    mma_tf32(c[mt][nt], alr[mt][0], alr[mt][1], alr[mt][2], alr[mt][3],
                             bh[nt][0], bh[nt][1]);
                }
        }
        __syncthreads();
    }

    // ---- epilogue ----
#pragma unroll
    for (int mt = 0; mt < 4; mt++) {
        int r0 = m0 + wm * 64 + mt * 16 + g;
        int r1 = r0 + 8;
#pragma unroll
        for (int nt = 0; nt < 4; nt++) {
            int c0 = n0 + wn * 32 + nt * 8 + tg * 2;
            if (MODE == 0) {
                // scatter into g_ztu[((b*H + h)*N + n)*DH + d]
#pragma unroll
                for (int e = 0; e < 4; e++) {
                    int row = (e >= 2) ? r1 : r0;
                    int col = c0 + (e & 1);
                    int b = row >> 11, nq = row & (Nn - 1);
                    int h = col >> 6, d = col & (DH - 1);
                    g_ztu[(((size_t)(b * Hh + h)) * Nn + nq) * DH + d] = c[mt][nt][e];
                }
            } else {
                Cout[(size_t)r0 * DIM + c0]     = c[mt][nt][0];
                Cout[(size_t)r0 * DIM + c0 + 1] = c[mt][nt][1];
                Cout[(size_t)r1 * DIM + c0]     = c[mt][nt][2];
                Cout[(size_t)r1 * DIM + c0 + 1] = c[mt][nt][3];
            }
        }
    }
}

// ---------------------------------------------------------------------------
// Flash attention.  Q=K=V = g_ztu[bh].  Grid (N/64, B*H), 128 threads.
// Warp w owns Q rows [16w, 16w+16).  tf32 mma for S=QK^T and O=PV.
// Scale folded into Q load (x0.125, exact).
// ---------------------------------------------------------------------------
__global__ __launch_bounds__(128)
void attn_kernel() {
    extern __shared__ uint32_t sm[];
    constexpr int LDQ = 68;  // 68 % 32 == 4 -> conflict-free A frags
    constexpr int LDV = 72;  // 72 % 32 == 8 -> conflict-free PV B frags
    uint32_t* Qs  = sm;                 // 64*68
    uint32_t* KVs = Qs + 64 * LDQ;      // 64*72
    uint32_t* Ps  = KVs + 64 * LDV;     // 64*68

    const int tid  = threadIdx.x;
    const int lane = tid & 31;
    const int warp = tid >> 5;
    const int g    = lane >> 2;
    const int tg   = lane & 3;
    const int qb   = blockIdx.x;
    const int bh   = blockIdx.y;

    const float* base = g_ztu + (size_t)bh * Nn * DH;

    // load + scale + convert Q tile (64 x 64)
#pragma unroll
    for (int i = 0; i < 8; i++) {
        int idx = tid + i * 128;
        int r = idx >> 4, c4 = (idx & 15) << 2;
        float4 v = *(const float4*)(base + (size_t)(qb * 64 + r) * DH + c4);
        int o = r * LDQ + c4;
        Qs[o + 0] = f2tf(v.x * 0.125f);
        Qs[o + 1] = f2tf(v.y * 0.125f);
        Qs[o + 2] = f2tf(v.z * 0.125f);
        Qs[o + 3] = f2tf(v.w * 0.125f);
    }
    __syncthreads();

    // hoist Q fragments (invariant over kv loop)
    uint32_t qa[8][4];
#pragma unroll
    for (int ks = 0; ks < 8; ks++) {
        int rb = (warp * 16 + g) * LDQ + ks * 8 + tg;
        qa[ks][0] = Qs[rb];
        qa[ks][1] = Qs[rb + 8 * LDQ];
        qa[ks][2] = Qs[rb + 4];
        qa[ks][3] = Qs[rb + 8 * LDQ + 4];
    }

    float mprev0 = -1e30f, mprev1 = -1e30f;
    float lsum0 = 0.0f, lsum1 = 0.0f;
    float o[8][4];
#pragma unroll
    for (int dt = 0; dt < 8; dt++)
#pragma unroll
        for (int e = 0; e < 4; e++) o[dt][e] = 0.0f;

    for (int kv = 0; kv < Nn / 64; kv++) {
        __syncthreads();  // prior iteration done with KVs
        // load KV tile (64 x 64), convert to tf32
#pragma unroll
        for (int i = 0; i < 8; i++) {
            int idx = tid + i * 128;
            int r = idx >> 4, c4 = (idx & 15) << 2;
            float4 v = *(const float4*)(base + (size_t)(kv * 64 + r) * DH + c4);
            int ofs = r * LDV + c4;
            KVs[ofs + 0] = f2tf(v.x);
            KVs[ofs + 1] = f2tf(v.y);
            KVs[ofs + 2] = f2tf(v.z);
            KVs[ofs + 3] = f2tf(v.w);
        }
        __syncthreads();

        // ---- S = Q K^T (16 x 64 per warp) ----
        float s[8][4];
#pragma unroll
        for (int nt = 0; nt < 8; nt++)
#pragma unroll
            for (int e = 0; e < 4; e++) s[nt][e] = 0.0f;
#pragma unroll
        for (int ks = 0; ks < 8; ks++) {
#pragma unroll
            for (int nt = 0; nt < 8; nt++) {
                uint32_t b0 = KVs[(nt * 8 + g) * LDV + ks * 8 + tg];
                uint32_t b1 = KVs[(nt * 8 + g) * LDV + ks * 8 + tg + 4];
                mma_tf32(s[nt], qa[ks][0], qa[ks][1], qa[ks][2], qa[ks][3], b0, b1);
            }
        }

        // ---- online softmax ----
        float mx0 = -1e30f, mx1 = -1e30f;
#pragma unroll
        for (int nt = 0; nt < 8; nt++) {
            mx0 = fmaxf(mx0, fmaxf(s[nt][0], s[nt][1]));
            mx1 = fmaxf(mx1, fmaxf(s[nt][2], s[nt][3]));
        }
        mx0 = fmaxf(mx0, __shfl_xor_sync(0xffffffffu, mx0, 1));
        mx0 = fmaxf(mx0, __shfl_xor_sync(0xffffffffu, mx0, 2));
        mx1 = fmaxf(mx1, __shfl_xor_sync(0xffffffffu, mx1, 1));
        mx1 = fmaxf(mx1, __shfl_xor_sync(0xffffffffu, mx1, 2));

        float mn0 = fmaxf(mprev0, mx0);
        float mn1 = fmaxf(mprev1, mx1);
        float a0 = __expf(mprev0 - mn0);
        float a1 = __expf(mprev1 - mn1);

        float rs0 = 0.0f, rs1 = 0.0f;
        int prow0 = (warp * 16 + g) * LDQ + tg * 2;
        int prow1 = prow0 + 8 * LDQ;
#pragma unroll
        for (int nt = 0; nt < 8; nt++) {
            float p0 = __expf(s[nt][0] - mn0);
            float p1 = __expf(s[nt][1] - mn0);
            float p2 = __expf(s[nt][2] - mn1);
            float p3 = __expf(s[nt][3] - mn1);
            rs0 += p0 + p1;
            rs1 += p2 + p3;
            Ps[prow0 + nt * 8 + 0] = f2tf(p0);
            Ps[prow0 + nt * 8 + 1] = f2tf(p1);
            Ps[prow1 + nt * 8 + 0] = f2tf(p2);
            Ps[prow1 + nt * 8 + 1] = f2tf(p3);
        }
        rs0 += __shfl_xor_sync(0xffffffffu, rs0, 1);
        rs0 += __shfl_xor_sync(0xffffffffu, rs0, 2);
        rs1 += __shfl_xor_sync(0xffffffffu, rs1, 1);
        rs1 += __shfl_xor_sync(0xffffffffu, rs1, 2);

        lsum0 = lsum0 * a0 + rs0;
        lsum1 = lsum1 * a1 + rs1;
        mprev0 = mn0;
        mprev1 = mn1;

#pragma unroll
        for (int dt = 0; dt < 8; dt++) {
            o[dt][0] *= a0;
            o[dt][1] *= a0;
            o[dt][2] *= a1;
            o[dt][3] *= a1;
        }
        __syncwarp();

        // ---- O += P V ----
#pragma unroll
        for (int ks = 0; ks < 8; ks++) {
            int pr = (warp * 16 + g) * LDQ + ks * 8 + tg;
            uint32_t pa0 = Ps[pr];
            uint32_t pa1 = Ps[pr + 8 * LDQ];
            uint32_t pa2 = Ps[pr + 4];
            uint32_t pa3 = Ps[pr + 8 * LDQ + 4];
#pragma unroll
            for (int dt = 0; dt < 8; dt++) {
                uint32_t b0 = KVs[(ks * 8 + tg) * LDV + dt * 8 + g];
                uint32_t b1 = KVs[(ks * 8 + tg + 4) * LDV + dt * 8 + g];
                mma_tf32(o[dt], pa0, pa1, pa2, pa3, b0, b1);
            }
        }
    }

    // ---- epilogue: normalize, store to g_ssa[b, n, h*64+d] ----
    float i0 = 1.0f / lsum0;
    float i1 = 1.0f / lsum1;
    int b = bh >> 4, h = bh & 15;
    int r0 = qb * 64 + warp * 16 + g;
    size_t base0 = ((size_t)b * Nn + r0) * DIM + h * DH;
    size_t base1 = base0 + (size_t)8 * DIM;
#pragma unroll
    for (int dt = 0; dt < 8; dt++) {
        int d = dt * 8 + tg * 2;
        g_ssa[base0 + d]     = o[dt][0] * i0;
        g_ssa[base0 + d + 1] = o[dt][1] * i0;
        g_ssa[base1 + d]     = o[dt][2] * i1;
        g_ssa[base1 + d + 1] = o[dt][3] * i1;
    }
}

// ---------------------------------------------------------------------------
extern "C" void kernel_launch(void* const* d_in, const int* in_sizes, int n_in,
                              void* d_out, int out_size) {
    const float* ZT = (const float*)d_in[0];  // [B, N, DIM]
    const float* W  = (const float*)d_in[1];  // [KP, DIM]
    float* out = (float*)d_out;               // [B, N, DIM] fp32

    const int smem_g1 = (128 * 36 * 2 + 128 * 36 * 2) * 4;   // 73728
    const int smem_g3 = (128 * 36 * 2 + 32 * 136 * 2) * 4;   // 71680
    const int smem_at = (64 * 68 + 64 * 72 + 64 * 68) * 4;   // 53248

    cudaFuncSetAttribute(gemm_tf32x3<1, 0>,
                         cudaFuncAttributeMaxDynamicSharedMemorySize, smem_g1);
    cudaFuncSetAttribute(gemm_tf32x3<0, 1>,
                         cudaFuncAttributeMaxDynamicSharedMemorySize, smem_g3);
    cudaFuncSetAttribute(attn_kernel,
                         cudaFuncAttributeMaxDynamicSharedMemorySize, smem_at);

    // 1) ZTU = ZT @ W^T  (scattered to [b,h,n,d])
    gemm_tf32x3<1, 0><<<dim3(DIM / 128, (Bb * Nn) / 128), 256, smem_g1>>>(ZT, W, nullptr);
    // 2) flash attention -> g_ssa [b,n,kp]
    attn_kernel<<<dim3(Nn / 64, Bb * Hh), 128, smem_at>>>();
    // 3) out = SSA @ W
    gemm_tf32x3<0, 1><<<dim3(DIM / 128, (Bb * Nn) / 128), 256, smem_g3>>>(nullptr, W, out);
}

// round 5
// speedup vs baseline: 1.2471x; 1.2471x over previous
#include <cuda_runtime.h>
#include <cuda_bf16.h>
#include <cstdint>

// Problem constants
constexpr int Bb  = 4;
constexpr int Nn  = 2048;
constexpr int DIM = 1024;
constexpr int Hh  = 16;
constexpr int DH  = 64;
// scale = DH^-0.5 = 0.125 (exact power of two)

// Scratch (allocation-free rule: __device__ globals)
__device__ float g_ztu[(size_t)Bb * Hh * Nn * DH];     // [b,h,n,d]  32 MB
__device__ float g_ssa[(size_t)Bb * Nn * DIM];         // [b,n,k]    32 MB
// Pre-split, pair-packed bf16 planes of W (built once per launch by pack_w):
//   Wn[r][p] : pairs along c   (row = kp)  -> B operand of projection GEMM
//   Wt[r][p] : pairs along kp  (row = c)   -> B operand of output GEMM
__device__ uint32_t g_Wn_hi[(size_t)DIM * (DIM / 2)];
__device__ uint32_t g_Wn_lo[(size_t)DIM * (DIM / 2)];
__device__ uint32_t g_Wt_hi[(size_t)DIM * (DIM / 2)];
__device__ uint32_t g_Wt_lo[(size_t)DIM * (DIM / 2)];

__device__ __forceinline__ uint32_t f2tf(float x) {
    uint32_t r;
    asm("cvt.rna.tf32.f32 %0, %1;" : "=r"(r) : "f"(x));
    return r;
}

__device__ __forceinline__ void mma_tf32(float* c,
                                         uint32_t a0, uint32_t a1, uint32_t a2, uint32_t a3,
                                         uint32_t b0, uint32_t b1) {
    asm volatile(
        "mma.sync.aligned.m16n8k8.row.col.f32.tf32.tf32.f32 "
        "{%0,%1,%2,%3},{%4,%5,%6,%7},{%8,%9},{%0,%1,%2,%3};"
        : "+f"(c[0]), "+f"(c[1]), "+f"(c[2]), "+f"(c[3])
        : "r"(a0), "r"(a1), "r"(a2), "r"(a3), "r"(b0), "r"(b1));
}

__device__ __forceinline__ void mma_bf16(float* c, const uint32_t* a,
                                         uint32_t b0, uint32_t b1) {
    asm volatile(
        "mma.sync.aligned.m16n8k16.row.col.f32.bf16.bf16.f32 "
        "{%0,%1,%2,%3},{%4,%5,%6,%7},{%8,%9},{%0,%1,%2,%3};"
        : "+f"(c[0]), "+f"(c[1]), "+f"(c[2]), "+f"(c[3])
        : "r"(a[0]), "r"(a[1]), "r"(a[2]), "r"(a[3]), "r"(b0), "r"(b1));
}

// split x into bf16 hi+lo; pack two consecutive-k elements per uint32 (low = even k)
__device__ __forceinline__ void sp2(float x, float y, uint32_t& h, uint32_t& l) {
    __nv_bfloat16 hx = __float2bfloat16_rn(x);
    __nv_bfloat16 hy = __float2bfloat16_rn(y);
    float rx = x - __bfloat162float(hx);
    float ry = y - __bfloat162float(hy);
    __nv_bfloat16 lx = __float2bfloat16_rn(rx);
    __nv_bfloat16 ly = __float2bfloat16_rn(ry);
    h = ((uint32_t)__bfloat16_as_ushort(hy) << 16) | (uint32_t)__bfloat16_as_ushort(hx);
    l = ((uint32_t)__bfloat16_as_ushort(ly) << 16) | (uint32_t)__bfloat16_as_ushort(lx);
}

// ---------------------------------------------------------------------------
// Prep: split+pack W into both orientations.  524288 threads.
// ---------------------------------------------------------------------------
__global__ __launch_bounds__(256)
void pack_w(const float* __restrict__ W) {
    int idx = blockIdx.x * 256 + threadIdx.x;      // 1024*512
    int r = idx >> 9, p = idx & 511;
    // Wn: row r (=kp), pair along c
    float x = W[(size_t)r * DIM + 2 * p];
    float y = W[(size_t)r * DIM + 2 * p + 1];
    sp2(x, y, g_Wn_hi[idx], g_Wn_lo[idx]);
    // Wt: row r (=c), pair along kp
    float u = W[(size_t)(2 * p) * DIM + r];
    float v = W[(size_t)(2 * p + 1) * DIM + r];
    sp2(u, v, g_Wt_hi[idx], g_Wt_lo[idx]);
}

// ---------------------------------------------------------------------------
// bf16x3 GEMM (hi*hi + hi*lo + lo*hi).  BM=BN=128, BK=32 (2 k16-steps).
// 256 threads = 8 warps, warp tile 64x32.  Smem double-buffered, register
// prefetch, one __syncthreads per K-tile.
// MODE 0: C = ZT @ W^T, scatter epilogue into g_ztu[b,h,n,d]  (B = Wn planes)
// MODE 1: C = g_ssa @ W, row-major epilogue to Cout           (B = Wt planes)
// ---------------------------------------------------------------------------
template <int MODE>
__global__ __launch_bounds__(256, 1)
void gemm_bf16x3(const float* __restrict__ Ain, float* __restrict__ Cout) {
    extern __shared__ uint32_t sm[];
    constexpr int LDS2  = 20;               // 16 pairs + pad -> conflict-free frags
    constexpr int PLANE = 128 * LDS2;       // 2560
    constexpr int BUF   = 4 * PLANE;        // Ah,Al,Bh,Bl

    const float*    A   = (MODE == 0) ? Ain : g_ssa;
    const uint32_t* Bhg = (MODE == 0) ? g_Wn_hi : g_Wt_hi;
    const uint32_t* Blg = (MODE == 0) ? g_Wn_lo : g_Wt_lo;

    const int tid  = threadIdx.x;
    const int lane = tid & 31;
    const int warp = tid >> 5;
    const int g    = lane >> 2;
    const int tg   = lane & 3;
    const int wm   = warp >> 2;   // 0..1
    const int wn   = warp & 3;    // 0..3
    const int m0   = blockIdx.y * 128;
    const int n0   = blockIdx.x * 128;

    float c[4][4][4];
#pragma unroll
    for (int mt = 0; mt < 4; mt++)
#pragma unroll
        for (int nt = 0; nt < 4; nt++)
#pragma unroll
            for (int e = 0; e < 4; e++) c[mt][nt][e] = 0.0f;

    float4 aS[4];
    uint4  bhS[2], blS[2];

    // ---- stage tile kt into registers ----
    auto loadT = [&](int kt) {
#pragma unroll
        for (int i = 0; i < 4; i++) {
            int idx = tid + i * 256;
            int r = idx >> 3, c4 = (idx & 7) << 2;
            aS[i] = *(const float4*)(A + (size_t)(m0 + r) * DIM + kt * 32 + c4);
        }
#pragma unroll
        for (int i = 0; i < 2; i++) {
            int idx = tid + i * 256;
            int r = idx >> 2, p4 = (idx & 3) << 2;
            bhS[i] = *(const uint4*)(Bhg + (size_t)(n0 + r) * (DIM / 2) + kt * 16 + p4);
            blS[i] = *(const uint4*)(Blg + (size_t)(n0 + r) * (DIM / 2) + kt * 16 + p4);
        }
    };
    // ---- split/convert registers -> smem buffer ----
    auto storeT = [&](int buf) {
        uint32_t* Ah = sm + buf * BUF;
        uint32_t* Al = Ah + PLANE;
        uint32_t* Bh = Al + PLANE;
        uint32_t* Bl = Bh + PLANE;
#pragma unroll
        for (int i = 0; i < 4; i++) {
            int idx = tid + i * 256;
            int r = idx >> 3, c2 = (idx & 7) << 1;
            int o = r * LDS2 + c2;
            sp2(aS[i].x, aS[i].y, Ah[o], Al[o]);
            sp2(aS[i].z, aS[i].w, Ah[o + 1], Al[o + 1]);
        }
#pragma unroll
        for (int i = 0; i < 2; i++) {
            int idx = tid + i * 256;
            int r = idx >> 2, p4 = (idx & 3) << 2;
            *(uint4*)(Bh + r * LDS2 + p4) = bhS[i];
            *(uint4*)(Bl + r * LDS2 + p4) = blS[i];
        }
    };

    loadT(0);
    storeT(0);

    for (int kt = 0; kt < DIM / 32; kt++) {
        __syncthreads();
        if (kt < DIM / 32 - 1) loadT(kt + 1);   // LDGs hidden behind compute

        const uint32_t* Ah = sm + (kt & 1) * BUF;
        const uint32_t* Al = Ah + PLANE;
        const uint32_t* Bh = Al + PLANE;
        const uint32_t* Bl = Bh + PLANE;
#pragma unroll
        for (int ks = 0; ks < 2; ks++) {
            uint32_t ah[4][4], al[4][4], bh[4][2], bl[4][2];
#pragma unroll
            for (int mt = 0; mt < 4; mt++) {
                int rb = (wm * 64 + mt * 16 + g) * LDS2 + ks * 8 + tg;
                ah[mt][0] = Ah[rb];
                ah[mt][1] = Ah[rb + 8 * LDS2];
                ah[mt][2] = Ah[rb + 4];
                ah[mt][3] = Ah[rb + 8 * LDS2 + 4];
                al[mt][0] = Al[rb];
                al[mt][1] = Al[rb + 8 * LDS2];
                al[mt][2] = Al[rb + 4];
                al[mt][3] = Al[rb + 8 * LDS2 + 4];
            }
#pragma unroll
            for (int nt = 0; nt < 4; nt++) {
                int rb = (wn * 32 + nt * 8 + g) * LDS2 + ks * 8 + tg;
                bh[nt][0] = Bh[rb];
                bh[nt][1] = Bh[rb + 4];
                bl[nt][0] = Bl[rb];
                bl[nt][1] = Bl[rb + 4];
            }
#pragma unroll
            for (int mt = 0; mt < 4; mt++)
#pragma unroll
                for (int nt = 0; nt < 4; nt++) {
                    mma_bf16(c[mt][nt], ah[mt], bh[nt][0], bh[nt][1]);
                    mma_bf16(c[mt][nt], ah[mt], bl[nt][0], bl[nt][1]);
                    mma_bf16(c[mt][nt], al[mt], bh[nt][0], bh[nt][1]);
                }
        }
        if (kt < DIM / 32 - 1) storeT((kt + 1) & 1);
    }

    // ---- epilogue ----
#pragma unroll
    for (int mt = 0; mt < 4; mt++) {
        int r0 = m0 + wm * 64 + mt * 16 + g;
        int r1 = r0 + 8;
#pragma unroll
        for (int nt = 0; nt < 4; nt++) {
            int c0 = n0 + wn * 32 + nt * 8 + tg * 2;
            if (MODE == 0) {
#pragma unroll
                for (int e = 0; e < 4; e++) {
                    int row = (e >= 2) ? r1 : r0;
                    int col = c0 + (e & 1);
                    int b = row >> 11, nq = row & (Nn - 1);
                    int h = col >> 6, d = col & (DH - 1);
                    g_ztu[(((size_t)(b * Hh + h)) * Nn + nq) * DH + d] = c[mt][nt][e];
                }
            } else {
                Cout[(size_t)r0 * DIM + c0]     = c[mt][nt][0];
                Cout[(size_t)r0 * DIM + c0 + 1] = c[mt][nt][1];
                Cout[(size_t)r1 * DIM + c0]     = c[mt][nt][2];
                Cout[(size_t)r1 * DIM + c0 + 1] = c[mt][nt][3];
            }
        }
    }
}

// ---------------------------------------------------------------------------
// Flash attention.  Q=K=V = g_ztu[bh].  Grid (N/128, B*H), 256 threads.
// 128-row Q tile (warp w owns rows 16w..16w+15), 64-row KV tile,
// double-buffered KV smem + register prefetch, one sync per KV tile.
// tf32 mma for S=QK^T and O=PV.  Scale folded into Q (x0.125, exact).
// ---------------------------------------------------------------------------
__global__ __launch_bounds__(256, 1)
void attn_kernel() {
    extern __shared__ uint32_t sm[];
    constexpr int LDQ = 68;  // conflict-free A frags
    constexpr int LDV = 72;  // conflict-free PV B frags
    uint32_t* Qs  = sm;                       // 128*68
    uint32_t* KV0 = Qs + 128 * LDQ;           // 64*72
    uint32_t* KV1 = KV0 + 64 * LDV;           // 64*72
    uint32_t* Ps  = KV1 + 64 * LDV;           // 128*68

    const int tid  = threadIdx.x;
    const int lane = tid & 31;
    const int warp = tid >> 5;
    const int g    = lane >> 2;
    const int tg   = lane & 3;
    const int qb   = blockIdx.x;
    const int bh   = blockIdx.y;

    const float* base = g_ztu + (size_t)bh * Nn * DH;

    // load + scale + convert Q tile (128 x 64)
#pragma unroll
    for (int i = 0; i < 8; i++) {
        int idx = tid + i * 256;
        int r = idx >> 4, c4 = (idx & 15) << 2;
        float4 v = *(const float4*)(base + (size_t)(qb * 128 + r) * DH + c4);
        int o = r * LDQ + c4;
        Qs[o + 0] = f2tf(v.x * 0.125f);
        Qs[o + 1] = f2tf(v.y * 0.125f);
        Qs[o + 2] = f2tf(v.z * 0.125f);
        Qs[o + 3] = f2tf(v.w * 0.125f);
    }
    __syncthreads();

    // hoist Q fragments (invariant over kv loop)
    uint32_t qa[8][4];
#pragma unroll
    for (int ks = 0; ks < 8; ks++) {
        int rb = (warp * 16 + g) * LDQ + ks * 8 + tg;
        qa[ks][0] = Qs[rb];
        qa[ks][1] = Qs[rb + 8 * LDQ];
        qa[ks][2] = Qs[rb + 4];
        qa[ks][3] = Qs[rb + 8 * LDQ + 4];
    }

    float mprev0 = -1e30f, mprev1 = -1e30f;
    float lsum0 = 0.0f, lsum1 = 0.0f;
    float o[8][4];
#pragma unroll
    for (int dt = 0; dt < 8; dt++)
#pragma unroll
        for (int e = 0; e < 4; e++) o[dt][e] = 0.0f;

    // register prefetch staging for KV tile (64 x 64)
    float4 kvS[4];
    auto prefetch = [&](int kv) {
#pragma unroll
        for (int i = 0; i < 4; i++) {
            int idx = tid + i * 256;
            int r = idx >> 4, c4 = (idx & 15) << 2;
            kvS[i] = *(const float4*)(base + (size_t)(kv * 64 + r) * DH + c4);
        }
    };
    prefetch(0);

    for (int kv = 0; kv < Nn / 64; kv++) {
        uint32_t* KVs = (kv & 1) ? KV1 : KV0;
        // convert staged regs -> KV buffer (other buffer may still be in use)
#pragma unroll
        for (int i = 0; i < 4; i++) {
            int idx = tid + i * 256;
            int r = idx >> 4, c4 = (idx & 15) << 2;
            int ofs = r * LDV + c4;
            KVs[ofs + 0] = f2tf(kvS[i].x);
            KVs[ofs + 1] = f2tf(kvS[i].y);
            KVs[ofs + 2] = f2tf(kvS[i].z);
            KVs[ofs + 3] = f2tf(kvS[i].w);
        }
        __syncthreads();
        if (kv < Nn / 64 - 1) prefetch(kv + 1);   // LDGs hidden behind compute

        // ---- S = Q K^T (16 x 64 per warp) ----
        float s[8][4];
#pragma unroll
        for (int nt = 0; nt < 8; nt++)
#pragma unroll
            for (int e = 0; e < 4; e++) s[nt][e] = 0.0f;
#pragma unroll
        for (int ks = 0; ks < 8; ks++) {
#pragma unroll
            for (int nt = 0; nt < 8; nt++) {
                uint32_t b0 = KVs[(nt * 8 + g) * LDV + ks * 8 + tg];
                uint32_t b1 = KVs[(nt * 8 + g) * LDV + ks * 8 + tg + 4];
                mma_tf32(s[nt], qa[ks][0], qa[ks][1], qa[ks][2], qa[ks][3], b0, b1);
            }
        }

        // ---- online softmax ----
        float mx0 = -1e30f, mx1 = -1e30f;
#pragma unroll
        for (int nt = 0; nt < 8; nt++) {
            mx0 = fmaxf(mx0, fmaxf(s[nt][0], s[nt][1]));
            mx1 = fmaxf(mx1, fmaxf(s[nt][2], s[nt][3]));
        }
        mx0 = fmaxf(mx0, __shfl_xor_sync(0xffffffffu, mx0, 1));
        mx0 = fmaxf(mx0, __shfl_xor_sync(0xffffffffu, mx0, 2));
        mx1 = fmaxf(mx1, __shfl_xor_sync(0xffffffffu, mx1, 1));
        mx1 = fmaxf(mx1, __shfl_xor_sync(0xffffffffu, mx1, 2));

        float mn0 = fmaxf(mprev0, mx0);
        float mn1 = fmaxf(mprev1, mx1);
        float a0 = __expf(mprev0 - mn0);
        float a1 = __expf(mprev1 - mn1);

        float rs0 = 0.0f, rs1 = 0.0f;
        int prow0 = (warp * 16 + g) * LDQ + tg * 2;
        int prow1 = prow0 + 8 * LDQ;
#pragma unroll
        for (int nt = 0; nt < 8; nt++) {
            float p0 = __expf(s[nt][0] - mn0);
            float p1 = __expf(s[nt][1] - mn0);
            float p2 = __expf(s[nt][2] - mn1);
            float p3 = __expf(s[nt][3] - mn1);
            rs0 += p0 + p1;
            rs1 += p2 + p3;
            Ps[prow0 + nt * 8 + 0] = f2tf(p0);
            Ps[prow0 + nt * 8 + 1] = f2tf(p1);
            Ps[prow1 + nt * 8 + 0] = f2tf(p2);
            Ps[prow1 + nt * 8 + 1] = f2tf(p3);
        }
        rs0 += __shfl_xor_sync(0xffffffffu, rs0, 1);
        rs0 += __shfl_xor_sync(0xffffffffu, rs0, 2);
        rs1 += __shfl_xor_sync(0xffffffffu, rs1, 1);
        rs1 += __shfl_xor_sync(0xffffffffu, rs1, 2);

        lsum0 = lsum0 * a0 + rs0;
        lsum1 = lsum1 * a1 + rs1;
        mprev0 = mn0;
        mprev1 = mn1;

#pragma unroll
        for (int dt = 0; dt < 8; dt++) {
            o[dt][0] *= a0;
            o[dt][1] *= a0;
            o[dt][2] *= a1;
            o[dt][3] *= a1;
        }
        __syncwarp();   // P rows are per-warp private; order stores before loads

        // ---- O += P V ----
#pragma unroll
        for (int ks = 0; ks < 8; ks++) {
            int pr = (warp * 16 + g) * LDQ + ks * 8 + tg;
            uint32_t pa[4];
            pa[0] = Ps[pr];
            pa[1] = Ps[pr + 8 * LDQ];
            pa[2] = Ps[pr + 4];
            pa[3] = Ps[pr + 8 * LDQ + 4];
#pragma unroll
            for (int dt = 0; dt < 8; dt++) {
                uint32_t b0 = KVs[(ks * 8 + tg) * LDV + dt * 8 + g];
                uint32_t b1 = KVs[(ks * 8 + tg + 4) * LDV + dt * 8 + g];
                mma_tf32(o[dt], pa[0], pa[1], pa[2], pa[3], b0, b1);
            }
        }
    }

    // ---- epilogue: normalize, store to g_ssa[b, n, h*64+d] ----
    float i0 = 1.0f / lsum0;
    float i1 = 1.0f / lsum1;
    int b = bh >> 4, h = bh & 15;
    int r0 = qb * 128 + warp * 16 + g;
    size_t base0 = ((size_t)b * Nn + r0) * DIM + h * DH;
    size_t base1 = base0 + (size_t)8 * DIM;
#pragma unroll
    for (int dt = 0; dt < 8; dt++) {
        int d = dt * 8 + tg * 2;
        g_ssa[base0 + d]     = o[dt][0] * i0;
        g_ssa[base0 + d + 1] = o[dt][1] * i0;
        g_ssa[base1 + d]     = o[dt][2] * i1;
        g_ssa[base1 + d + 1] = o[dt][3] * i1;
    }
}

// ---------------------------------------------------------------------------
extern "C" void kernel_launch(void* const* d_in, const int* in_sizes, int n_in,
                              void* d_out, int out_size) {
    const float* ZT = (const float*)d_in[0];  // [B, N, DIM]
    const float* W  = (const float*)d_in[1];  // [KP, DIM]
    float* out = (float*)d_out;               // [B, N, DIM] fp32

    const int smem_gemm = 2 * 4 * 2560 * 4;                         // 81920
    const int smem_attn = (128 * 68 + 2 * 64 * 72 + 128 * 68) * 4;  // 106496

    cudaFuncSetAttribute(gemm_bf16x3<0>,
                         cudaFuncAttributeMaxDynamicSharedMemorySize, smem_gemm);
    cudaFuncSetAttribute(gemm_bf16x3<1>,
                         cudaFuncAttributeMaxDynamicSharedMemorySize, smem_gemm);
    cudaFuncSetAttribute(attn_kernel,
                         cudaFuncAttributeMaxDynamicSharedMemorySize, smem_attn);

    // 0) split+pack W (both orientations) into bf16 hi/lo planes
    pack_w<<<(DIM * (DIM / 2)) / 256, 256>>>(W);
    // 1) ZTU = ZT @ W^T  (scattered to [b,h,n,d])
    gemm_bf16x3<0><<<dim3(DIM / 128, (Bb * Nn) / 128), 256, smem_gemm>>>(ZT, nullptr);
    // 2) flash attention -> g_ssa [b,n,kp]
    attn_kernel<<<dim3(Nn / 128, Bb * Hh), 256, smem_attn>>>();
    // 3) out = SSA @ W
    gemm_bf16x3<1><<<dim3(DIM / 128, (Bb * Nn) / 128), 256, smem_gemm>>>(nullptr, out);
}

// round 6
// speedup vs baseline: 1.3180x; 1.0569x over previous
#include <cuda_runtime.h>
#include <cuda_bf16.h>
#include <cstdint>

// Problem constants
constexpr int Bb  = 4;
constexpr int Nn  = 2048;
constexpr int DIM = 1024;
constexpr int Hh  = 16;
constexpr int DH  = 64;
// scale = DH^-0.5 = 0.125 (exact power of two), applied inside softmax

// Scratch (allocation-free rule: __device__ globals)
__device__ uint32_t g_ztu[(size_t)Bb * Hh * Nn * DH];  // [b,h,n,d] tf32 bits, 32 MB
__device__ float    g_ssa[(size_t)Bb * Nn * DIM];      // [b,n,k]   fp32,      32 MB
// Pre-split, pair-packed bf16 planes of W (built once per launch by pack_w):
//   Wn[r][p] : pairs along c   (row = kp)  -> B operand of projection GEMM
//   Wt[r][p] : pairs along kp  (row = c)   -> B operand of output GEMM
__device__ uint32_t g_Wn_hi[(size_t)DIM * (DIM / 2)];
__device__ uint32_t g_Wn_lo[(size_t)DIM * (DIM / 2)];
__device__ uint32_t g_Wt_hi[(size_t)DIM * (DIM / 2)];
__device__ uint32_t g_Wt_lo[(size_t)DIM * (DIM / 2)];

__device__ __forceinline__ uint32_t f2tf(float x) {
    uint32_t r;
    asm("cvt.rna.tf32.f32 %0, %1;" : "=r"(r) : "f"(x));
    return r;
}

__device__ __forceinline__ void mma_tf32(float* c,
                                         uint32_t a0, uint32_t a1, uint32_t a2, uint32_t a3,
                                         uint32_t b0, uint32_t b1) {
    asm volatile(
        "mma.sync.aligned.m16n8k8.row.col.f32.tf32.tf32.f32 "
        "{%0,%1,%2,%3},{%4,%5,%6,%7},{%8,%9},{%0,%1,%2,%3};"
        : "+f"(c[0]), "+f"(c[1]), "+f"(c[2]), "+f"(c[3])
        : "r"(a0), "r"(a1), "r"(a2), "r"(a3), "r"(b0), "r"(b1));
}

__device__ __forceinline__ void mma_bf16(float* c, const uint32_t* a,
                                         uint32_t b0, uint32_t b1) {
    asm volatile(
        "mma.sync.aligned.m16n8k16.row.col.f32.bf16.bf16.f32 "
        "{%0,%1,%2,%3},{%4,%5,%6,%7},{%8,%9},{%0,%1,%2,%3};"
        : "+f"(c[0]), "+f"(c[1]), "+f"(c[2]), "+f"(c[3])
        : "r"(a[0]), "r"(a[1]), "r"(a[2]), "r"(a[3]), "r"(b0), "r"(b1));
}

// split x into bf16 hi+lo; pack two consecutive-k elements per uint32 (low = even k)
__device__ __forceinline__ void sp2(float x, float y, uint32_t& h, uint32_t& l) {
    __nv_bfloat16 hx = __float2bfloat16_rn(x);
    __nv_bfloat16 hy = __float2bfloat16_rn(y);
    float rx = x - __bfloat162float(hx);
    float ry = y - __bfloat162float(hy);
    __nv_bfloat16 lx = __float2bfloat16_rn(rx);
    __nv_bfloat16 ly = __float2bfloat16_rn(ry);
    h = ((uint32_t)__bfloat16_as_ushort(hy) << 16) | (uint32_t)__bfloat16_as_ushort(hx);
    l = ((uint32_t)__bfloat16_as_ushort(ly) << 16) | (uint32_t)__bfloat16_as_ushort(lx);
}

// ---------------------------------------------------------------------------
// Prep: split+pack W into both orientations.  524288 threads.
// ---------------------------------------------------------------------------
__global__ __launch_bounds__(256)
void pack_w(const float* __restrict__ W) {
    int idx = blockIdx.x * 256 + threadIdx.x;      // 1024*512
    int r = idx >> 9, p = idx & 511;
    // Wn: row r (=kp), pair along c
    float x = W[(size_t)r * DIM + 2 * p];
    float y = W[(size_t)r * DIM + 2 * p + 1];
    sp2(x, y, g_Wn_hi[idx], g_Wn_lo[idx]);
    // Wt: row r (=c), pair along kp
    float u = W[(size_t)(2 * p) * DIM + r];
    float v = W[(size_t)(2 * p + 1) * DIM + r];
    sp2(u, v, g_Wt_hi[idx], g_Wt_lo[idx]);
}

// ---------------------------------------------------------------------------
// bf16x3 GEMM (hi*hi + hi*lo + lo*hi).  BM=BN=128, BK=32 (2 k16-steps).
// 256 threads = 8 warps, warp tile 64x32.  Smem double-buffered, register
// prefetch, one __syncthreads per K-tile.
// MODE 0: C = ZT @ W^T, scatter tf32 bits into g_ztu[b,h,n,d]  (B = Wn planes)
// MODE 1: C = g_ssa @ W, row-major epilogue to Cout            (B = Wt planes)
// ---------------------------------------------------------------------------
template <int MODE>
__global__ __launch_bounds__(256, 1)
void gemm_bf16x3(const float* __restrict__ Ain, float* __restrict__ Cout) {
    extern __shared__ uint32_t sm[];
    constexpr int LDS2  = 20;               // 16 pairs + pad -> conflict-free frags
    constexpr int PLANE = 128 * LDS2;       // 2560
    constexpr int BUF   = 4 * PLANE;        // Ah,Al,Bh,Bl

    const float*    A   = (MODE == 0) ? Ain : g_ssa;
    const uint32_t* Bhg = (MODE == 0) ? g_Wn_hi : g_Wt_hi;
    const uint32_t* Blg = (MODE == 0) ? g_Wn_lo : g_Wt_lo;

    const int tid  = threadIdx.x;
    const int lane = tid & 31;
    const int warp = tid >> 5;
    const int g    = lane >> 2;
    const int tg   = lane & 3;
    const int wm   = warp >> 2;   // 0..1
    const int wn   = warp & 3;    // 0..3
    const int m0   = blockIdx.y * 128;
    const int n0   = blockIdx.x * 128;

    float c[4][4][4];
#pragma unroll
    for (int mt = 0; mt < 4; mt++)
#pragma unroll
        for (int nt = 0; nt < 4; nt++)
#pragma unroll
            for (int e = 0; e < 4; e++) c[mt][nt][e] = 0.0f;

    float4 aS[4];
    uint4  bhS[2], blS[2];

    // ---- stage tile kt into registers ----
    auto loadT = [&](int kt) {
#pragma unroll
        for (int i = 0; i < 4; i++) {
            int idx = tid + i * 256;
            int r = idx >> 3, c4 = (idx & 7) << 2;
            aS[i] = *(const float4*)(A + (size_t)(m0 + r) * DIM + kt * 32 + c4);
        }
#pragma unroll
        for (int i = 0; i < 2; i++) {
            int idx = tid + i * 256;
            int r = idx >> 2, p4 = (idx & 3) << 2;
            bhS[i] = *(const uint4*)(Bhg + (size_t)(n0 + r) * (DIM / 2) + kt * 16 + p4);
            blS[i] = *(const uint4*)(Blg + (size_t)(n0 + r) * (DIM / 2) + kt * 16 + p4);
        }
    };
    // ---- split/convert registers -> smem buffer ----
    auto storeT = [&](int buf) {
        uint32_t* Ah = sm + buf * BUF;
        uint32_t* Al = Ah + PLANE;
        uint32_t* Bh = Al + PLANE;
        uint32_t* Bl = Bh + PLANE;
#pragma unroll
        for (int i = 0; i < 4; i++) {
            int idx = tid + i * 256;
            int r = idx >> 3, c2 = (idx & 7) << 1;
            int o = r * LDS2 + c2;
            sp2(aS[i].x, aS[i].y, Ah[o], Al[o]);
            sp2(aS[i].z, aS[i].w, Ah[o + 1], Al[o + 1]);
        }
#pragma unroll
        for (int i = 0; i < 2; i++) {
            int idx = tid + i * 256;
            int r = idx >> 2, p4 = (idx & 3) << 2;
            *(uint4*)(Bh + r * LDS2 + p4) = bhS[i];
            *(uint4*)(Bl + r * LDS2 + p4) = blS[i];
        }
    };

    loadT(0);
    storeT(0);

    for (int kt = 0; kt < DIM / 32; kt++) {
        __syncthreads();
        if (kt < DIM / 32 - 1) loadT(kt + 1);   // LDGs hidden behind compute

        const uint32_t* Ah = sm + (kt & 1) * BUF;
        const uint32_t* Al = Ah + PLANE;
        const uint32_t* Bh = Al + PLANE;
        const uint32_t* Bl = Bh + PLANE;
#pragma unroll
        for (int ks = 0; ks < 2; ks++) {
            uint32_t ah[4][4], al[4][4], bh[4][2], bl[4][2];
#pragma unroll
            for (int mt = 0; mt < 4; mt++) {
                int rb = (wm * 64 + mt * 16 + g) * LDS2 + ks * 8 + tg;
                ah[mt][0] = Ah[rb];
                ah[mt][1] = Ah[rb + 8 * LDS2];
                ah[mt][2] = Ah[rb + 4];
                ah[mt][3] = Ah[rb + 8 * LDS2 + 4];
                al[mt][0] = Al[rb];
                al[mt][1] = Al[rb + 8 * LDS2];
                al[mt][2] = Al[rb + 4];
                al[mt][3] = Al[rb + 8 * LDS2 + 4];
            }
#pragma unroll
            for (int nt = 0; nt < 4; nt++) {
                int rb = (wn * 32 + nt * 8 + g) * LDS2 + ks * 8 + tg;
                bh[nt][0] = Bh[rb];
                bh[nt][1] = Bh[rb + 4];
                bl[nt][0] = Bl[rb];
                bl[nt][1] = Bl[rb + 4];
            }
#pragma unroll
            for (int mt = 0; mt < 4; mt++)
#pragma unroll
                for (int nt = 0; nt < 4; nt++) {
                    mma_bf16(c[mt][nt], ah[mt], bh[nt][0], bh[nt][1]);
                    mma_bf16(c[mt][nt], ah[mt], bl[nt][0], bl[nt][1]);
                    mma_bf16(c[mt][nt], al[mt], bh[nt][0], bh[nt][1]);
                }
        }
        if (kt < DIM / 32 - 1) storeT((kt + 1) & 1);
    }

    // ---- epilogue ----
#pragma unroll
    for (int mt = 0; mt < 4; mt++) {
        int r0 = m0 + wm * 64 + mt * 16 + g;
        int r1 = r0 + 8;
#pragma unroll
        for (int nt = 0; nt < 4; nt++) {
            int c0 = n0 + wn * 32 + nt * 8 + tg * 2;
            if (MODE == 0) {
                // scatter tf32 bits into g_ztu[((b*H + h)*N + n)*DH + d]
#pragma unroll
                for (int e = 0; e < 4; e++) {
                    int row = (e >= 2) ? r1 : r0;
                    int col = c0 + (e & 1);
                    int b = row >> 11, nq = row & (Nn - 1);
                    int h = col >> 6, d = col & (DH - 1);
                    g_ztu[(((size_t)(b * Hh + h)) * Nn + nq) * DH + d] = f2tf(c[mt][nt][e]);
                }
            } else {
                Cout[(size_t)r0 * DIM + c0]     = c[mt][nt][0];
                Cout[(size_t)r0 * DIM + c0 + 1] = c[mt][nt][1];
                Cout[(size_t)r1 * DIM + c0]     = c[mt][nt][2];
                Cout[(size_t)r1 * DIM + c0 + 1] = c[mt][nt][3];
            }
        }
    }
}

// ---------------------------------------------------------------------------
// Flash attention.  Q=K=V = g_ztu[bh] (pre-converted tf32 bits).
// Grid (N/128, B*H), 256 threads, 2 CTAs/SM (4 warps/SMSP).
// 128-row Q tile (warp w owns rows 16w..16w+15), 64-row KV tile,
// double-buffered KV smem + register prefetch, one sync per KV tile.
// Scale 0.125 folded into softmax exponent (exact).
// ---------------------------------------------------------------------------
__global__ __launch_bounds__(256, 2)
void attn_kernel() {
    extern __shared__ uint32_t sm[];
    constexpr int LDQ = 68;  // %4==0 (uint4 ok), %32==4 -> conflict-free A frags
    constexpr int LDV = 72;  // %4==0, %32==8 -> conflict-free PV B frags
    uint32_t* Qs  = sm;                       // 128*68
    uint32_t* KV0 = Qs + 128 * LDQ;           // 64*72
    uint32_t* KV1 = KV0 + 64 * LDV;           // 64*72
    uint32_t* Ps  = KV1 + 64 * LDV;           // 128*68

    const int tid  = threadIdx.x;
    const int lane = tid & 31;
    const int warp = tid >> 5;
    const int g    = lane >> 2;
    const int tg   = lane & 3;
    const int qb   = blockIdx.x;
    const int bh   = blockIdx.y;

    // 0.125 * log2(e): softmax(0.125*s) via exp2f
    const float C = 0.18033688011112042f;

    const uint32_t* base = g_ztu + (size_t)bh * Nn * DH;

    // copy Q tile (128 x 64, already tf32 bits)
#pragma unroll
    for (int i = 0; i < 8; i++) {
        int idx = tid + i * 256;
        int r = idx >> 4, c4 = (idx & 15) << 2;
        uint4 v = *(const uint4*)(base + (size_t)(qb * 128 + r) * DH + c4);
        *(uint4*)(Qs + r * LDQ + c4) = v;
    }
    __syncthreads();

    // hoist Q fragments (invariant over kv loop)
    uint32_t qa[8][4];
#pragma unroll
    for (int ks = 0; ks < 8; ks++) {
        int rb = (warp * 16 + g) * LDQ + ks * 8 + tg;
        qa[ks][0] = Qs[rb];
        qa[ks][1] = Qs[rb + 8 * LDQ];
        qa[ks][2] = Qs[rb + 4];
        qa[ks][3] = Qs[rb + 8 * LDQ + 4];
    }

    float mprev0 = -1e30f, mprev1 = -1e30f;
    float lsum0 = 0.0f, lsum1 = 0.0f;
    float o[8][4];
#pragma unroll
    for (int dt = 0; dt < 8; dt++)
#pragma unroll
        for (int e = 0; e < 4; e++) o[dt][e] = 0.0f;

    // register prefetch staging for KV tile (64 x 64 tf32 words)
    uint4 kvS[4];
    auto prefetch = [&](int kv) {
#pragma unroll
        for (int i = 0; i < 4; i++) {
            int idx = tid + i * 256;
            int r = idx >> 4, c4 = (idx & 15) << 2;
            kvS[i] = *(const uint4*)(base + (size_t)(kv * 64 + r) * DH + c4);
        }
    };
    prefetch(0);

    for (int kv = 0; kv < Nn / 64; kv++) {
        uint32_t* KVs = (kv & 1) ? KV1 : KV0;
        // staged regs -> KV buffer (other buffer may still be in use)
#pragma unroll
        for (int i = 0; i < 4; i++) {
            int idx = tid + i * 256;
            int r = idx >> 4, c4 = (idx & 15) << 2;
            *(uint4*)(KVs + r * LDV + c4) = kvS[i];
        }
        __syncthreads();
        if (kv < Nn / 64 - 1) prefetch(kv + 1);   // LDGs hidden behind compute

        // ---- S = Q K^T (16 x 64 per warp, raw scores) ----
        float s[8][4];
#pragma unroll
        for (int nt = 0; nt < 8; nt++)
#pragma unroll
            for (int e = 0; e < 4; e++) s[nt][e] = 0.0f;
#pragma unroll
        for (int ks = 0; ks < 8; ks++) {
#pragma unroll
            for (int nt = 0; nt < 8; nt++) {
                uint32_t b0 = KVs[(nt * 8 + g) * LDV + ks * 8 + tg];
                uint32_t b1 = KVs[(nt * 8 + g) * LDV + ks * 8 + tg + 4];
                mma_tf32(s[nt], qa[ks][0], qa[ks][1], qa[ks][2], qa[ks][3], b0, b1);
            }
        }

        // ---- online softmax (scale folded into exponent) ----
        float mx0 = -1e30f, mx1 = -1e30f;
#pragma unroll
        for (int nt = 0; nt < 8; nt++) {
            mx0 = fmaxf(mx0, fmaxf(s[nt][0], s[nt][1]));
            mx1 = fmaxf(mx1, fmaxf(s[nt][2], s[nt][3]));
        }
        mx0 = fmaxf(mx0, __shfl_xor_sync(0xffffffffu, mx0, 1));
        mx0 = fmaxf(mx0, __shfl_xor_sync(0xffffffffu, mx0, 2));
        mx1 = fmaxf(mx1, __shfl_xor_sync(0xffffffffu, mx1, 1));
        mx1 = fmaxf(mx1, __shfl_xor_sync(0xffffffffu, mx1, 2));

        float mn0 = fmaxf(mprev0, mx0);
        float mn1 = fmaxf(mprev1, mx1);
        float a0 = exp2f(C * (mprev0 - mn0));
        float a1 = exp2f(C * (mprev1 - mn1));

        float rs0 = 0.0f, rs1 = 0.0f;
        int prow0 = (warp * 16 + g) * LDQ + tg * 2;
        int prow1 = prow0 + 8 * LDQ;
#pragma unroll
        for (int nt = 0; nt < 8; nt++) {
            float p0 = exp2f(C * (s[nt][0] - mn0));
            float p1 = exp2f(C * (s[nt][1] - mn0));
            float p2 = exp2f(C * (s[nt][2] - mn1));
            float p3 = exp2f(C * (s[nt][3] - mn1));
            rs0 += p0 + p1;
            rs1 += p2 + p3;
            Ps[prow0 + nt * 8 + 0] = f2tf(p0);
            Ps[prow0 + nt * 8 + 1] = f2tf(p1);
            Ps[prow1 + nt * 8 + 0] = f2tf(p2);
            Ps[prow1 + nt * 8 + 1] = f2tf(p3);
        }
        rs0 += __shfl_xor_sync(0xffffffffu, rs0, 1);
        rs0 += __shfl_xor_sync(0xffffffffu, rs0, 2);
        rs1 += __shfl_xor_sync(0xffffffffu, rs1, 1);
        rs1 += __shfl_xor_sync(0xffffffffu, rs1, 2);

        lsum0 = lsum0 * a0 + rs0;
        lsum1 = lsum1 * a1 + rs1;
        mprev0 = mn0;
        mprev1 = mn1;

#pragma unroll
        for (int dt = 0; dt < 8; dt++) {
            o[dt][0] *= a0;
            o[dt][1] *= a0;
            o[dt][2] *= a1;
            o[dt][3] *= a1;
        }
        __syncwarp();   // P rows are per-warp private; order stores before loads

        // ---- O += P V ----
#pragma unroll
        for (int ks = 0; ks < 8; ks++) {
            int pr = (warp * 16 + g) * LDQ + ks * 8 + tg;
            uint32_t pa[4];
            pa[0] = Ps[pr];
            pa[1] = Ps[pr + 8 * LDQ];
            pa[2] = Ps[pr + 4];
            pa[3] = Ps[pr + 8 * LDQ + 4];
#pragma unroll
            for (int dt = 0; dt < 8; dt++) {
                uint32_t b0 = KVs[(ks * 8 + tg) * LDV + dt * 8 + g];
                uint32_t b1 = KVs[(ks * 8 + tg + 4) * LDV + dt * 8 + g];
                mma_tf32(o[dt], pa[0], pa[1], pa[2], pa[3], b0, b1);
            }
        }
    }

    // ---- epilogue: normalize, store to g_ssa[b, n, h*64+d] ----
    float i0 = 1.0f / lsum0;
    float i1 = 1.0f / lsum1;
    int b = bh >> 4, h = bh & 15;
    int r0 = qb * 128 + warp * 16 + g;
    size_t base0 = ((size_t)b * Nn + r0) * DIM + h * DH;
    size_t base1 = base0 + (size_t)8 * DIM;
#pragma unroll
    for (int dt = 0; dt < 8; dt++) {
        int d = dt * 8 + tg * 2;
        g_ssa[base0 + d]     = o[dt][0] * i0;
        g_ssa[base0 + d + 1] = o[dt][1] * i0;
        g_ssa[base1 + d]     = o[dt][2] * i1;
        g_ssa[base1 + d + 1] = o[dt][3] * i1;
    }
}

// ---------------------------------------------------------------------------
extern "C" void kernel_launch(void* const* d_in, const int* in_sizes, int n_in,
                              void* d_out, int out_size) {
    const float* ZT = (const float*)d_in[0];  // [B, N, DIM]
    const float* W  = (const float*)d_in[1];  // [KP, DIM]
    float* out = (float*)d_out;               // [B, N, DIM] fp32

    const int smem_gemm = 2 * 4 * 2560 * 4;                         // 81920
    const int smem_attn = (128 * 68 + 2 * 64 * 72 + 128 * 68) * 4;  // 106496

    cudaFuncSetAttribute(gemm_bf16x3<0>,
                         cudaFuncAttributeMaxDynamicSharedMemorySize, smem_gemm);
    cudaFuncSetAttribute(gemm_bf16x3<1>,
                         cudaFuncAttributeMaxDynamicSharedMemorySize, smem_gemm);
    cudaFuncSetAttribute(attn_kernel,
                         cudaFuncAttributeMaxDynamicSharedMemorySize, smem_attn);

    // 0) split+pack W (both orientations) into bf16 hi/lo planes
    pack_w<<<(DIM * (DIM / 2)) / 256, 256>>>(W);
    // 1) ZTU = ZT @ W^T  (tf32 bits scattered to [b,h,n,d])
    gemm_bf16x3<0><<<dim3(DIM / 128, (Bb * Nn) / 128), 256, smem_gemm>>>(ZT, nullptr);
    // 2) flash attention -> g_ssa [b,n,kp]
    attn_kernel<<<dim3(Nn / 128, Bb * Hh), 256, smem_attn>>>();
    // 3) out = SSA @ W
    gemm_bf16x3<1><<<dim3(DIM / 128, (Bb * Nn) / 128), 256, smem_gemm>>>(nullptr, out);
}

// round 7
// speedup vs baseline: 1.3405x; 1.0171x over previous
#include <cuda_runtime.h>
#include <cuda_bf16.h>
#include <cstdint>

// Problem constants
constexpr int Bb  = 4;
constexpr int Nn  = 2048;
constexpr int DIM = 1024;
constexpr int Hh  = 16;
constexpr int DH  = 64;
// scale = DH^-0.5 = 0.125 (exact power of two), applied inside softmax

// Scratch (allocation-free rule: __device__ globals)
__device__ uint32_t g_ztu[(size_t)Bb * Hh * Nn * DH];  // [b,h,n,d] tf32 bits, 32 MB
__device__ float    g_ssa[(size_t)Bb * Nn * DIM];      // [b,n,k]   fp32,      32 MB
// Pre-split, pair-packed bf16 planes of W (built once per launch by pack_w)
__device__ uint32_t g_Wn_hi[(size_t)DIM * (DIM / 2)];
__device__ uint32_t g_Wn_lo[(size_t)DIM * (DIM / 2)];
__device__ uint32_t g_Wt_hi[(size_t)DIM * (DIM / 2)];
__device__ uint32_t g_Wt_lo[(size_t)DIM * (DIM / 2)];

__device__ __forceinline__ uint32_t f2tf(float x) {
    uint32_t r;
    asm("cvt.rna.tf32.f32 %0, %1;" : "=r"(r) : "f"(x));
    return r;
}

__device__ __forceinline__ void mma_tf32(float* c,
                                         uint32_t a0, uint32_t a1, uint32_t a2, uint32_t a3,
                                         uint32_t b0, uint32_t b1) {
    asm volatile(
        "mma.sync.aligned.m16n8k8.row.col.f32.tf32.tf32.f32 "
        "{%0,%1,%2,%3},{%4,%5,%6,%7},{%8,%9},{%0,%1,%2,%3};"
        : "+f"(c[0]), "+f"(c[1]), "+f"(c[2]), "+f"(c[3])
        : "r"(a0), "r"(a1), "r"(a2), "r"(a3), "r"(b0), "r"(b1));
}

__device__ __forceinline__ void mma_bf16(float* c, const uint32_t* a,
                                         uint32_t b0, uint32_t b1) {
    asm volatile(
        "mma.sync.aligned.m16n8k16.row.col.f32.bf16.bf16.f32 "
        "{%0,%1,%2,%3},{%4,%5,%6,%7},{%8,%9},{%0,%1,%2,%3};"
        : "+f"(c[0]), "+f"(c[1]), "+f"(c[2]), "+f"(c[3])
        : "r"(a[0]), "r"(a[1]), "r"(a[2]), "r"(a[3]), "r"(b0), "r"(b1));
}

__device__ __forceinline__ void cpasync16(uint32_t smem_dst, const void* gsrc) {
    asm volatile("cp.async.cg.shared.global [%0], [%1], 16;"
                 :: "r"(smem_dst), "l"(gsrc));
}
__device__ __forceinline__ void cp_commit() {
    asm volatile("cp.async.commit_group;");
}
__device__ __forceinline__ void cp_wait0() {
    asm volatile("cp.async.wait_group 0;");
}

// split x into bf16 hi+lo; pack two consecutive-k elements per uint32 (low = even k)
__device__ __forceinline__ void sp2(float x, float y, uint32_t& h, uint32_t& l) {
    __nv_bfloat16 hx = __float2bfloat16_rn(x);
    __nv_bfloat16 hy = __float2bfloat16_rn(y);
    float rx = x - __bfloat162float(hx);
    float ry = y - __bfloat162float(hy);
    __nv_bfloat16 lx = __float2bfloat16_rn(rx);
    __nv_bfloat16 ly = __float2bfloat16_rn(ry);
    h = ((uint32_t)__bfloat16_as_ushort(hy) << 16) | (uint32_t)__bfloat16_as_ushort(hx);
    l = ((uint32_t)__bfloat16_as_ushort(ly) << 16) | (uint32_t)__bfloat16_as_ushort(lx);
}

// ---------------------------------------------------------------------------
// Prep: split+pack W into both orientations.
// ---------------------------------------------------------------------------
__global__ __launch_bounds__(256)
void pack_w(const float* __restrict__ W) {
    int idx = blockIdx.x * 256 + threadIdx.x;      // 1024*512
    int r = idx >> 9, p = idx & 511;
    float x = W[(size_t)r * DIM + 2 * p];
    float y = W[(size_t)r * DIM + 2 * p + 1];
    sp2(x, y, g_Wn_hi[idx], g_Wn_lo[idx]);
    float u = W[(size_t)(2 * p) * DIM + r];
    float v = W[(size_t)(2 * p + 1) * DIM + r];
    sp2(u, v, g_Wt_hi[idx], g_Wt_lo[idx]);
}

// ---------------------------------------------------------------------------
// bf16x3 GEMM.  BM=BN=128, BK=32.  256 threads, warp tile 64x32.
// A: register-staged + sp2 split.  B planes: cp.async direct (pre-packed).
// Double-buffered smem, one __syncthreads per K-tile.
// ---------------------------------------------------------------------------
template <int MODE>
__global__ __launch_bounds__(256, 1)
void gemm_bf16x3(const float* __restrict__ Ain, float* __restrict__ Cout) {
    extern __shared__ uint32_t sm[];
    constexpr int LDS2  = 20;               // 16 pairs + pad -> conflict-free frags
    constexpr int PLANE = 128 * LDS2;       // 2560
    constexpr int BUF   = 4 * PLANE;        // Ah,Al,Bh,Bl

    const float*    A   = (MODE == 0) ? Ain : g_ssa;
    const uint32_t* Bhg = (MODE == 0) ? g_Wn_hi : g_Wt_hi;
    const uint32_t* Blg = (MODE == 0) ? g_Wn_lo : g_Wt_lo;

    const int tid  = threadIdx.x;
    const int lane = tid & 31;
    const int warp = tid >> 5;
    const int g    = lane >> 2;
    const int tg   = lane & 3;
    const int wm   = warp >> 2;   // 0..1
    const int wn   = warp & 3;    // 0..3
    const int m0   = blockIdx.y * 128;
    const int n0   = blockIdx.x * 128;

    float c[4][4][4];
#pragma unroll
    for (int mt = 0; mt < 4; mt++)
#pragma unroll
        for (int nt = 0; nt < 4; nt++)
#pragma unroll
            for (int e = 0; e < 4; e++) c[mt][nt][e] = 0.0f;

    float4 aS[4];

    auto loadA = [&](int kt) {
#pragma unroll
        for (int i = 0; i < 4; i++) {
            int idx = tid + i * 256;
            int r = idx >> 3, c4 = (idx & 7) << 2;
            aS[i] = *(const float4*)(A + (size_t)(m0 + r) * DIM + kt * 32 + c4);
        }
    };
    auto storeA = [&](int buf) {
        uint32_t* Ah = sm + buf * BUF;
        uint32_t* Al = Ah + PLANE;
#pragma unroll
        for (int i = 0; i < 4; i++) {
            int idx = tid + i * 256;
            int r = idx >> 3, c2 = (idx & 7) << 1;
            int o = r * LDS2 + c2;
            sp2(aS[i].x, aS[i].y, Ah[o], Al[o]);
            sp2(aS[i].z, aS[i].w, Ah[o + 1], Al[o + 1]);
        }
    };
    auto issueB = [&](int kt, int buf) {
        uint32_t* Bh = sm + buf * BUF + 2 * PLANE;
        uint32_t* Bl = Bh + PLANE;
#pragma unroll
        for (int i = 0; i < 2; i++) {
            int idx = tid + i * 256;
            int r = idx >> 2, p4 = (idx & 3) << 2;
            cpasync16((uint32_t)__cvta_generic_to_shared(Bh + r * LDS2 + p4),
                      Bhg + (size_t)(n0 + r) * (DIM / 2) + kt * 16 + p4);
            cpasync16((uint32_t)__cvta_generic_to_shared(Bl + r * LDS2 + p4),
                      Blg + (size_t)(n0 + r) * (DIM / 2) + kt * 16 + p4);
        }
        cp_commit();
    };

    issueB(0, 0);
    loadA(0);
    storeA(0);

    for (int kt = 0; kt < DIM / 32; kt++) {
        cp_wait0();
        __syncthreads();
        if (kt < DIM / 32 - 1) {
            issueB(kt + 1, (kt + 1) & 1);   // into buffer last read at kt-1: safe
            loadA(kt + 1);                  // LDGs hidden behind compute
        }

        const uint32_t* Ah = sm + (kt & 1) * BUF;
        const uint32_t* Al = Ah + PLANE;
        const uint32_t* Bh = Al + PLANE;
        const uint32_t* Bl = Bh + PLANE;
#pragma unroll
        for (int ks = 0; ks < 2; ks++) {
            uint32_t ah[4][4], al[4][4], bh[4][2], bl[4][2];
#pragma unroll
            for (int mt = 0; mt < 4; mt++) {
                int rb = (wm * 64 + mt * 16 + g) * LDS2 + ks * 8 + tg;
                ah[mt][0] = Ah[rb];
                ah[mt][1] = Ah[rb + 8 * LDS2];
                ah[mt][2] = Ah[rb + 4];
                ah[mt][3] = Ah[rb + 8 * LDS2 + 4];
                al[mt][0] = Al[rb];
                al[mt][1] = Al[rb + 8 * LDS2];
                al[mt][2] = Al[rb + 4];
                al[mt][3] = Al[rb + 8 * LDS2 + 4];
            }
#pragma unroll
            for (int nt = 0; nt < 4; nt++) {
                int rb = (wn * 32 + nt * 8 + g) * LDS2 + ks * 8 + tg;
                bh[nt][0] = Bh[rb];
                bh[nt][1] = Bh[rb + 4];
                bl[nt][0] = Bl[rb];
                bl[nt][1] = Bl[rb + 4];
            }
#pragma unroll
            for (int mt = 0; mt < 4; mt++)
#pragma unroll
                for (int nt = 0; nt < 4; nt++) {
                    mma_bf16(c[mt][nt], ah[mt], bh[nt][0], bh[nt][1]);
                    mma_bf16(c[mt][nt], ah[mt], bl[nt][0], bl[nt][1]);
                    mma_bf16(c[mt][nt], al[mt], bh[nt][0], bh[nt][1]);
                }
        }
        if (kt < DIM / 32 - 1) storeA((kt + 1) & 1);
    }

    // ---- epilogue ----
#pragma unroll
    for (int mt = 0; mt < 4; mt++) {
        int r0 = m0 + wm * 64 + mt * 16 + g;
        int r1 = r0 + 8;
#pragma unroll
        for (int nt = 0; nt < 4; nt++) {
            int c0 = n0 + wn * 32 + nt * 8 + tg * 2;
            if (MODE == 0) {
#pragma unroll
                for (int e = 0; e < 4; e++) {
                    int row = (e >= 2) ? r1 : r0;
                    int col = c0 + (e & 1);
                    int b = row >> 11, nq = row & (Nn - 1);
                    int h = col >> 6, d = col & (DH - 1);
                    g_ztu[(((size_t)(b * Hh + h)) * Nn + nq) * DH + d] = f2tf(c[mt][nt][e]);
                }
            } else {
                Cout[(size_t)r0 * DIM + c0]     = c[mt][nt][0];
                Cout[(size_t)r0 * DIM + c0 + 1] = c[mt][nt][1];
                Cout[(size_t)r1 * DIM + c0]     = c[mt][nt][2];
                Cout[(size_t)r1 * DIM + c0 + 1] = c[mt][nt][3];
            }
        }
    }
}

// ---------------------------------------------------------------------------
// Flash attention.  Q=K=V = g_ztu[bh] (pre-converted tf32 bits).
// Grid (N/128, B*H), 256 threads, 2 CTAs/SM.  KV tiles via cp.async
// double-buffering (no register staging -> no spills at the 128-reg cap).
// Scale 0.125 folded into softmax exponent (exact).
// ---------------------------------------------------------------------------
__global__ __launch_bounds__(256, 2)
void attn_kernel() {
    extern __shared__ uint32_t sm[];
    constexpr int LDQ = 68;  // %32==4 -> conflict-free A frags
    constexpr int LDV = 72;  // %32==8 -> conflict-free PV B frags
    uint32_t* Qs  = sm;                       // 128*68
    uint32_t* KV0 = Qs + 128 * LDQ;           // 64*72
    uint32_t* KV1 = KV0 + 64 * LDV;           // 64*72
    uint32_t* Ps  = KV1 + 64 * LDV;           // 128*68

    const int tid  = threadIdx.x;
    const int lane = tid & 31;
    const int warp = tid >> 5;
    const int g    = lane >> 2;
    const int tg   = lane & 3;
    const int qb   = blockIdx.x;
    const int bh   = blockIdx.y;

    // 0.125 * log2(e): softmax(0.125*s) via exp2f
    const float C = 0.18033688011112042f;

    const uint32_t* base = g_ztu + (size_t)bh * Nn * DH;

    // copy Q tile (128 x 64, already tf32 bits)
#pragma unroll
    for (int i = 0; i < 8; i++) {
        int idx = tid + i * 256;
        int r = idx >> 4, c4 = (idx & 15) << 2;
        uint4 v = *(const uint4*)(base + (size_t)(qb * 128 + r) * DH + c4);
        *(uint4*)(Qs + r * LDQ + c4) = v;
    }

    // issue first KV tile while Q settles
    auto issue = [&](int kv) {
        uint32_t* KVd = (kv & 1) ? KV1 : KV0;
#pragma unroll
        for (int i = 0; i < 4; i++) {
            int idx = tid + i * 256;
            int r = idx >> 4, c4 = (idx & 15) << 2;
            cpasync16((uint32_t)__cvta_generic_to_shared(KVd + r * LDV + c4),
                      base + (size_t)(kv * 64 + r) * DH + c4);
        }
        cp_commit();
    };
    issue(0);
    __syncthreads();

    // hoist Q fragments (invariant over kv loop)
    uint32_t qa[8][4];
#pragma unroll
    for (int ks = 0; ks < 8; ks++) {
        int rb = (warp * 16 + g) * LDQ + ks * 8 + tg;
        qa[ks][0] = Qs[rb];
        qa[ks][1] = Qs[rb + 8 * LDQ];
        qa[ks][2] = Qs[rb + 4];
        qa[ks][3] = Qs[rb + 8 * LDQ + 4];
    }

    float mprev0 = -1e30f, mprev1 = -1e30f;
    float lsum0 = 0.0f, lsum1 = 0.0f;
    float o[8][4];
#pragma unroll
    for (int dt = 0; dt < 8; dt++)
#pragma unroll
        for (int e = 0; e < 4; e++) o[dt][e] = 0.0f;

    for (int kv = 0; kv < Nn / 64; kv++) {
        cp_wait0();          // tile kv complete (per-thread)
        __syncthreads();     // visible to all warps
        if (kv < Nn / 64 - 1) issue(kv + 1);   // other buffer: last read at kv-1, safe

        const uint32_t* KVs = (kv & 1) ? KV1 : KV0;

        // ---- S = Q K^T (16 x 64 per warp, raw scores) ----
        float s[8][4];
#pragma unroll
        for (int nt = 0; nt < 8; nt++)
#pragma unroll
            for (int e = 0; e < 4; e++) s[nt][e] = 0.0f;
#pragma unroll
        for (int ks = 0; ks < 8; ks++) {
#pragma unroll
            for (int nt = 0; nt < 8; nt++) {
                uint32_t b0 = KVs[(nt * 8 + g) * LDV + ks * 8 + tg];
                uint32_t b1 = KVs[(nt * 8 + g) * LDV + ks * 8 + tg + 4];
                mma_tf32(s[nt], qa[ks][0], qa[ks][1], qa[ks][2], qa[ks][3], b0, b1);
            }
        }

        // ---- online softmax (scale folded into exponent) ----
        float mx0 = -1e30f, mx1 = -1e30f;
#pragma unroll
        for (int nt = 0; nt < 8; nt++) {
            mx0 = fmaxf(mx0, fmaxf(s[nt][0], s[nt][1]));
            mx1 = fmaxf(mx1, fmaxf(s[nt][2], s[nt][3]));
        }
        mx0 = fmaxf(mx0, __shfl_xor_sync(0xffffffffu, mx0, 1));
        mx0 = fmaxf(mx0, __shfl_xor_sync(0xffffffffu, mx0, 2));
        mx1 = fmaxf(mx1, __shfl_xor_sync(0xffffffffu, mx1, 1));
        mx1 = fmaxf(mx1, __shfl_xor_sync(0xffffffffu, mx1, 2));

        float mn0 = fmaxf(mprev0, mx0);
        float mn1 = fmaxf(mprev1, mx1);
        float a0 = exp2f(C * (mprev0 - mn0));
        float a1 = exp2f(C * (mprev1 - mn1));

        float rs0 = 0.0f, rs1 = 0.0f;
        int prow0 = (warp * 16 + g) * LDQ + tg * 2;
        int prow1 = prow0 + 8 * LDQ;
#pragma unroll
        for (int nt = 0; nt < 8; nt++) {
            float p0 = exp2f(C * (s[nt][0] - mn0));
            float p1 = exp2f(C * (s[nt][1] - mn0));
            float p2 = exp2f(C * (s[nt][2] - mn1));
            float p3 = exp2f(C * (s[nt][3] - mn1));
            rs0 += p0 + p1;
            rs1 += p2 + p3;
            Ps[prow0 + nt * 8 + 0] = f2tf(p0);
            Ps[prow0 + nt * 8 + 1] = f2tf(p1);
            Ps[prow1 + nt * 8 + 0] = f2tf(p2);
            Ps[prow1 + nt * 8 + 1] = f2tf(p3);
        }
        rs0 += __shfl_xor_sync(0xffffffffu, rs0, 1);
        rs0 += __shfl_xor_sync(0xffffffffu, rs0, 2);
        rs1 += __shfl_xor_sync(0xffffffffu, rs1, 1);
        rs1 += __shfl_xor_sync(0xffffffffu, rs1, 2);

        lsum0 = lsum0 * a0 + rs0;
        lsum1 = lsum1 * a1 + rs1;
        mprev0 = mn0;
        mprev1 = mn1;

#pragma unroll
        for (int dt = 0; dt < 8; dt++) {
            o[dt][0] *= a0;
            o[dt][1] *= a0;
            o[dt][2] *= a1;
            o[dt][3] *= a1;
        }
        __syncwarp();   // P rows are per-warp private; order stores before loads

        // ---- O += P V ----
#pragma unroll
        for (int ks = 0; ks < 8; ks++) {
            int pr = (warp * 16 + g) * LDQ + ks * 8 + tg;
            uint32_t pa[4];
            pa[0] = Ps[pr];
            pa[1] = Ps[pr + 8 * LDQ];
            pa[2] = Ps[pr + 4];
            pa[3] = Ps[pr + 8 * LDQ + 4];
#pragma unroll
            for (int dt = 0; dt < 8; dt++) {
                uint32_t b0 = KVs[(ks * 8 + tg) * LDV + dt * 8 + g];
                uint32_t b1 = KVs[(ks * 8 + tg + 4) * LDV + dt * 8 + g];
                mma_tf32(o[dt], pa[0], pa[1], pa[2], pa[3], b0, b1);
            }
        }
    }

    // ---- epilogue: normalize, store to g_ssa[b, n, h*64+d] ----
    float i0 = 1.0f / lsum0;
    float i1 = 1.0f / lsum1;
    int b = bh >> 4, h = bh & 15;
    int r0 = qb * 128 + warp * 16 + g;
    size_t base0 = ((size_t)b * Nn + r0) * DIM + h * DH;
    size_t base1 = base0 + (size_t)8 * DIM;
#pragma unroll
    for (int dt = 0; dt < 8; dt++) {
        int d = dt * 8 + tg * 2;
        g_ssa[base0 + d]     = o[dt][0] * i0;
        g_ssa[base0 + d + 1] = o[dt][1] * i0;
        g_ssa[base1 + d]     = o[dt][2] * i1;
        g_ssa[base1 + d + 1] = o[dt][3] * i1;
    }
}

// ---------------------------------------------------------------------------
extern "C" void kernel_launch(void* const* d_in, const int* in_sizes, int n_in,
                              void* d_out, int out_size) {
    const float* ZT = (const float*)d_in[0];  // [B, N, DIM]
    const float* W  = (const float*)d_in[1];  // [KP, DIM]
    float* out = (float*)d_out;               // [B, N, DIM] fp32

    const int smem_gemm = 2 * 4 * 2560 * 4;                         // 81920
    const int smem_attn = (128 * 68 + 2 * 64 * 72 + 128 * 68) * 4;  // 106496

    cudaFuncSetAttribute(gemm_bf16x3<0>,
                         cudaFuncAttributeMaxDynamicSharedMemorySize, smem_gemm);
    cudaFuncSetAttribute(gemm_bf16x3<1>,
                         cudaFuncAttributeMaxDynamicSharedMemorySize, smem_gemm);
    cudaFuncSetAttribute(attn_kernel,
                         cudaFuncAttributeMaxDynamicSharedMemorySize, smem_attn);

    // 0) split+pack W (both orientations) into bf16 hi/lo planes
    pack_w<<<(DIM * (DIM / 2)) / 256, 256>>>(W);
    // 1) ZTU = ZT @ W^T  (tf32 bits scattered to [b,h,n,d])
    gemm_bf16x3<0><<<dim3(DIM / 128, (Bb * Nn) / 128), 256, smem_gemm>>>(ZT, nullptr);
    // 2) flash attention -> g_ssa [b,n,kp]
    attn_kernel<<<dim3(Nn / 128, Bb * Hh), 256, smem_attn>>>();
    // 3) out = SSA @ W
    gemm_bf16x3<1><<<dim3(DIM / 128, (Bb * Nn) / 128), 256, smem_gemm>>>(nullptr, out);
}